// round 1
// baseline (speedup 1.0000x reference)
#include <cuda_runtime.h>
#include <math.h>

#define EDIM 256
#define NHEAD 8
#define HDIM 32
#define BATCH 4
#define LQ 512
#define LKV 4096
#define NLAYER 4
#define NTQ (LQ*BATCH)     // 2048 query tokens
#define NTKV (LKV*BATCH)   // 16384 kv tokens

// ---------------- scratch (device globals; no allocation allowed) ----------------
__device__ float g_x  [NTQ*EDIM];              // layer input  [t, e], t = lq*B + b
__device__ float g_qh [BATCH*NHEAD*LQ*HDIM];   // q  [b,h,lq,d]
__device__ float g_kh [BATCH*NHEAD*LKV*HDIM];  // k  [b,h,lkv,d]
__device__ float g_vh [BATCH*NHEAD*LKV*HDIM];  // v  [b,h,lkv,d]
__device__ float g_oh [BATCH*NHEAD*LQ*HDIM];   // attn out [b,h,lq,d]
__device__ float g_of [NTQ*EDIM];              // attn out flattened [t,e]
__device__ float g_t1 [NTQ*EDIM];
__device__ float g_x1 [NTQ*EDIM];
__device__ float g_hh [NTQ*EDIM];
__device__ float g_t2 [NTQ*EDIM];

// ---------------- simple copy ----------------
__global__ void copy_kernel(const float* __restrict__ src, float* __restrict__ dst, int n){
    int i = blockIdx.x*blockDim.x + threadIdx.x;
    if (i < n) dst[i] = src[i];
}

// ---------------- GEMM + bias + scale + optional rotary + head scatter ----------------
// C[t, c] = sum_e A[t,e] * W[c,e] + bias[c]; then *scale; then rotary (pairs);
// scatter to out[((b*H + h)*L + l)*HD + d] with t = l*B + b, h = c/32, d = c%32.
// Tiles: BM=BN=128, BK=16, 256 threads, 8x8 micro-tile.
template<bool ROPE>
__global__ __launch_bounds__(256)
void gemm_rope_kernel(const float* __restrict__ A, const float* __restrict__ W,
                      const float* __restrict__ bias, const float* __restrict__ pos,
                      float* __restrict__ out, int L, float scale)
{
    const int row0 = blockIdx.x * 128;
    const int col0 = blockIdx.y * 128;
    __shared__ float As[16][132];
    __shared__ float Bs[16][132];
    const int tid = threadIdx.x;
    const int ty = tid >> 4, tx = tid & 15;

    float acc[8][8];
#pragma unroll
    for (int i = 0; i < 8; i++)
#pragma unroll
        for (int j = 0; j < 8; j++) acc[i][j] = 0.f;

    for (int k0 = 0; k0 < EDIM; k0 += 16) {
#pragma unroll
        for (int s = 0; s < 2; s++) {
            int f = tid + s*256;           // 0..511 float4 slots (128 rows x 4)
            int r  = f >> 2;
            int kq = (f & 3) << 2;
            float4 av = *(const float4*)(A + (size_t)(row0 + r)*EDIM + k0 + kq);
            As[kq+0][r]=av.x; As[kq+1][r]=av.y; As[kq+2][r]=av.z; As[kq+3][r]=av.w;
            float4 bv = *(const float4*)(W + (size_t)(col0 + r)*EDIM + k0 + kq);
            Bs[kq+0][r]=bv.x; Bs[kq+1][r]=bv.y; Bs[kq+2][r]=bv.z; Bs[kq+3][r]=bv.w;
        }
        __syncthreads();
#pragma unroll
        for (int k = 0; k < 16; k++) {
            float a[8], b[8];
            *(float4*)&a[0] = *(const float4*)&As[k][ty*8];
            *(float4*)&a[4] = *(const float4*)&As[k][ty*8+4];
            *(float4*)&b[0] = *(const float4*)&Bs[k][tx*8];
            *(float4*)&b[4] = *(const float4*)&Bs[k][tx*8+4];
#pragma unroll
            for (int i = 0; i < 8; i++)
#pragma unroll
                for (int j = 0; j < 8; j++)
                    acc[i][j] = fmaf(a[i], b[j], acc[i][j]);
        }
        __syncthreads();
    }

    const int c0 = col0 + tx*8;   // 8 consecutive output feature cols (even start)
    const int h  = c0 >> 5;
    const int d0 = c0 & 31;
    float bj[8];
#pragma unroll
    for (int j = 0; j < 8; j++) bj[j] = bias[c0 + j];

#pragma unroll
    for (int i = 0; i < 8; i++) {
        int t  = row0 + ty*8 + i;
        int l  = t >> 2;          // token position (B=4)
        int bb = t & 3;           // batch
        float v[8];
#pragma unroll
        for (int j = 0; j < 8; j++) v[j] = (acc[i][j] + bj[j]) * scale;
        if (ROPE) {
            const float* pp = pos + ((size_t)(bb*L + l)*EDIM + c0)*2;
#pragma unroll
            for (int jp = 0; jp < 4; jp++) {
                float4 cs = *(const float4*)(pp + jp*4); // cos_e,sin_e,cos_o,sin_o
                float ve = v[2*jp], vo = v[2*jp+1];
                v[2*jp]   = ve*cs.x - vo*cs.y;
                v[2*jp+1] = vo*cs.z + ve*cs.w;
            }
        }
        float* op = out + ((size_t)(bb*NHEAD + h)*L + l)*HDIM + d0;
        *(float4*)op       = make_float4(v[0],v[1],v[2],v[3]);
        *(float4*)(op + 4) = make_float4(v[4],v[5],v[6],v[7]);
    }
}

// ---------------- generic GEMM: out = A@W^T + bias (+res) (+relu) ----------------
// Tiles: BM=BN=64, BK=32, 256 threads, 4x4 micro-tile. Fixed K=N=256.
template<bool RELU, bool RES>
__global__ __launch_bounds__(256)
void gemm_gen_kernel(const float* __restrict__ A, const float* __restrict__ W,
                     const float* __restrict__ bias, const float* __restrict__ res,
                     float* __restrict__ out)
{
    const int row0 = blockIdx.x * 64;
    const int col0 = blockIdx.y * 64;
    __shared__ float As[32][68];
    __shared__ float Bs[32][68];
    const int tid = threadIdx.x;
    const int ty = tid >> 4, tx = tid & 15;

    float acc[4][4];
#pragma unroll
    for (int i = 0; i < 4; i++)
#pragma unroll
        for (int j = 0; j < 4; j++) acc[i][j] = 0.f;

    for (int k0 = 0; k0 < EDIM; k0 += 32) {
#pragma unroll
        for (int s = 0; s < 2; s++) {
            int f = tid + s*256;            // 0..511 (64 rows x 8 float4)
            int r  = f >> 3;
            int kq = (f & 7) << 2;
            float4 av = *(const float4*)(A + (size_t)(row0 + r)*EDIM + k0 + kq);
            As[kq+0][r]=av.x; As[kq+1][r]=av.y; As[kq+2][r]=av.z; As[kq+3][r]=av.w;
            float4 bv = *(const float4*)(W + (size_t)(col0 + r)*EDIM + k0 + kq);
            Bs[kq+0][r]=bv.x; Bs[kq+1][r]=bv.y; Bs[kq+2][r]=bv.z; Bs[kq+3][r]=bv.w;
        }
        __syncthreads();
#pragma unroll
        for (int k = 0; k < 32; k++) {
            float a[4], b[4];
            *(float4*)&a[0] = *(const float4*)&As[k][ty*4];
            *(float4*)&b[0] = *(const float4*)&Bs[k][tx*4];
#pragma unroll
            for (int i = 0; i < 4; i++)
#pragma unroll
                for (int j = 0; j < 4; j++)
                    acc[i][j] = fmaf(a[i], b[j], acc[i][j]);
        }
        __syncthreads();
    }

#pragma unroll
    for (int i = 0; i < 4; i++) {
        int t = row0 + ty*4 + i;
#pragma unroll
        for (int j = 0; j < 4; j++) {
            int c = col0 + tx*4 + j;
            float v = acc[i][j] + bias[c];
            if (RES)  v += res[(size_t)t*EDIM + c];
            if (RELU) v = fmaxf(v, 0.f);
            out[(size_t)t*EDIM + c] = v;
        }
    }
}

// ---------------- flash attention (online softmax), per (b,h) ----------------
// Block: 64 q rows; loop kv in tiles of 64. 256 threads as 16x16:
// thread(ty,tx): score rows 4*ty..+3, score cols 4*tx..+3; O ownership rows x d={2tx,2tx+1}.
__global__ __launch_bounds__(256)
void attn_kernel(const float* __restrict__ Q, const float* __restrict__ K,
                 const float* __restrict__ V, float* __restrict__ O)
{
    const int bh = blockIdx.y;
    const int q0 = blockIdx.x * 64;
    __shared__ float Qs[32][68];  // [d][row]   (k-major for outer-product)
    __shared__ float Ks[32][68];  // [d][col]
    __shared__ float Vs[64][34];  // [col][d]
    __shared__ float Ps[64][68];  // probs tile
    const int tid = threadIdx.x;
    const int ty = tid >> 4, tx = tid & 15;

#pragma unroll
    for (int s = 0; s < 2; s++) {
        int f = tid + s*256;
        int r  = f >> 3;
        int dq = (f & 7) << 2;
        float4 qv = *(const float4*)(Q + ((size_t)bh*LQ + q0 + r)*HDIM + dq);
        Qs[dq+0][r]=qv.x; Qs[dq+1][r]=qv.y; Qs[dq+2][r]=qv.z; Qs[dq+3][r]=qv.w;
    }

    float m[4], lsum[4], oa[4][2];
#pragma unroll
    for (int i = 0; i < 4; i++) { m[i] = -1e30f; lsum[i] = 0.f; oa[i][0] = 0.f; oa[i][1] = 0.f; }

    for (int kv0 = 0; kv0 < LKV; kv0 += 64) {
        __syncthreads();
#pragma unroll
        for (int s = 0; s < 2; s++) {
            int f = tid + s*256;
            int r  = f >> 3;
            int dq = (f & 7) << 2;
            float4 kv = *(const float4*)(K + ((size_t)bh*LKV + kv0 + r)*HDIM + dq);
            Ks[dq+0][r]=kv.x; Ks[dq+1][r]=kv.y; Ks[dq+2][r]=kv.z; Ks[dq+3][r]=kv.w;
            float4 vv = *(const float4*)(V + ((size_t)bh*LKV + kv0 + r)*HDIM + dq);
            Vs[r][dq+0]=vv.x; Vs[r][dq+1]=vv.y; Vs[r][dq+2]=vv.z; Vs[r][dq+3]=vv.w;
        }
        __syncthreads();

        // scores: outer product over d
        float sc[4][4];
#pragma unroll
        for (int i = 0; i < 4; i++)
#pragma unroll
            for (int j = 0; j < 4; j++) sc[i][j] = 0.f;
#pragma unroll
        for (int k = 0; k < 32; k++) {
            float4 q4 = *(const float4*)&Qs[k][ty*4];
            float4 k4 = *(const float4*)&Ks[k][tx*4];
            float qa[4] = {q4.x, q4.y, q4.z, q4.w};
            float kb[4] = {k4.x, k4.y, k4.z, k4.w};
#pragma unroll
            for (int i = 0; i < 4; i++)
#pragma unroll
                for (int j = 0; j < 4; j++)
                    sc[i][j] = fmaf(qa[i], kb[j], sc[i][j]);
        }

        // online softmax per row (16-thread row groups live within a half-warp)
#pragma unroll
        for (int i = 0; i < 4; i++) {
            float tmax = fmaxf(fmaxf(sc[i][0], sc[i][1]), fmaxf(sc[i][2], sc[i][3]));
#pragma unroll
            for (int off = 8; off; off >>= 1)
                tmax = fmaxf(tmax, __shfl_xor_sync(0xffffffffu, tmax, off, 16));
            float mnew = fmaxf(m[i], tmax);
            float corr = __expf(m[i] - mnew);
            float psum = 0.f;
#pragma unroll
            for (int j = 0; j < 4; j++) {
                float p = __expf(sc[i][j] - mnew);
                Ps[ty*4 + i][tx*4 + j] = p;
                psum += p;
            }
#pragma unroll
            for (int off = 8; off; off >>= 1)
                psum += __shfl_xor_sync(0xffffffffu, psum, off, 16);
            lsum[i] = lsum[i]*corr + psum;
            m[i] = mnew;
            oa[i][0] *= corr; oa[i][1] *= corr;
        }
        __syncthreads();

        // PV accumulate: O[row][2tx..2tx+1] += P[row][:] @ V[:][2tx..2tx+1]
#pragma unroll
        for (int c0 = 0; c0 < 64; c0 += 4) {
            float4 p0 = *(const float4*)&Ps[ty*4+0][c0];
            float4 p1 = *(const float4*)&Ps[ty*4+1][c0];
            float4 p2 = *(const float4*)&Ps[ty*4+2][c0];
            float4 p3 = *(const float4*)&Ps[ty*4+3][c0];
            float2 v0 = *(const float2*)&Vs[c0+0][tx*2];
            float2 v1 = *(const float2*)&Vs[c0+1][tx*2];
            float2 v2 = *(const float2*)&Vs[c0+2][tx*2];
            float2 v3 = *(const float2*)&Vs[c0+3][tx*2];
            oa[0][0] += p0.x*v0.x + p0.y*v1.x + p0.z*v2.x + p0.w*v3.x;
            oa[0][1] += p0.x*v0.y + p0.y*v1.y + p0.z*v2.y + p0.w*v3.y;
            oa[1][0] += p1.x*v0.x + p1.y*v1.x + p1.z*v2.x + p1.w*v3.x;
            oa[1][1] += p1.x*v0.y + p1.y*v1.y + p1.z*v2.y + p1.w*v3.y;
            oa[2][0] += p2.x*v0.x + p2.y*v1.x + p2.z*v2.x + p2.w*v3.x;
            oa[2][1] += p2.x*v0.y + p2.y*v1.y + p2.z*v2.y + p2.w*v3.y;
            oa[3][0] += p3.x*v0.x + p3.y*v1.x + p3.z*v2.x + p3.w*v3.x;
            oa[3][1] += p3.x*v0.y + p3.y*v1.y + p3.z*v2.y + p3.w*v3.y;
        }
    }

#pragma unroll
    for (int i = 0; i < 4; i++) {
        float inv = 1.f / lsum[i];
        float2 o2 = make_float2(oa[i][0]*inv, oa[i][1]*inv);
        *(float2*)(O + ((size_t)bh*LQ + q0 + ty*4 + i)*HDIM + tx*2) = o2;
    }
}

// ---------------- reshape [B,H,Lq,HD] -> [t=(l*B+b), e=(h*32+d)] ----------------
__global__ void reshape_kernel(const float* __restrict__ oh, float* __restrict__ of){
    int i = blockIdx.x*256 + threadIdx.x;   // over NTQ*EDIM
    int e = i & (EDIM-1);
    int t = i >> 8;
    int l = t >> 2, bb = t & 3;
    int h = e >> 5, d = e & 31;
    of[i] = oh[(((size_t)(bb*NHEAD + h))*LQ + l)*HDIM + d];
}

// ---------------- layernorm over E=256 (1 block per row, 256 threads) ----------------
__global__ void ln_kernel(const float* __restrict__ x, const float* __restrict__ g,
                          const float* __restrict__ b, float* __restrict__ out1,
                          float* __restrict__ out2)
{
    __shared__ float red[8];
    const int t = blockIdx.x, e = threadIdx.x;
    const int w = e >> 5, lane = e & 31;
    float v = x[(size_t)t*EDIM + e];

    float s = v;
#pragma unroll
    for (int off = 16; off; off >>= 1) s += __shfl_xor_sync(0xffffffffu, s, off);
    if (lane == 0) red[w] = s;
    __syncthreads();
    if (e < 32) {
        float r = (lane < 8) ? red[lane] : 0.f;
#pragma unroll
        for (int off = 4; off; off >>= 1) r += __shfl_xor_sync(0xffffffffu, r, off, 8);
        if (lane == 0) red[0] = r;
    }
    __syncthreads();
    float mean = red[0] * (1.f/EDIM);
    __syncthreads();

    float dv = v - mean;
    float s2 = dv*dv;
#pragma unroll
    for (int off = 16; off; off >>= 1) s2 += __shfl_xor_sync(0xffffffffu, s2, off);
    if (lane == 0) red[w] = s2;
    __syncthreads();
    if (e < 32) {
        float r = (lane < 8) ? red[lane] : 0.f;
#pragma unroll
        for (int off = 4; off; off >>= 1) r += __shfl_xor_sync(0xffffffffu, r, off, 8);
        if (lane == 0) red[0] = r;
    }
    __syncthreads();
    float var = red[0] * (1.f/EDIM);

    float y = dv * rsqrtf(var + 1e-5f) * g[e] + b[e];
    out1[(size_t)t*EDIM + e] = y;
    if (out2) out2[(size_t)t*EDIM + e] = y;
}

// ---------------- launch ----------------
extern "C" void kernel_launch(void* const* d_in, const int* in_sizes, int n_in,
                              void* d_out, int out_size)
{
    (void)in_sizes; (void)n_in; (void)out_size;
    const float* query = (const float*)d_in[0];
    const float* value = (const float*)d_in[1];
    const float* qpos  = (const float*)d_in[2];
    const float* vpos  = (const float*)d_in[3];
    const float* Wqkv  = (const float*)d_in[4];
    const float* bqkv  = (const float*)d_in[5];
    const float* Wo    = (const float*)d_in[6];
    const float* bo    = (const float*)d_in[7];
    const float* ln1g  = (const float*)d_in[8];
    const float* ln1b  = (const float*)d_in[9];
    const float* W1    = (const float*)d_in[10];
    const float* b1    = (const float*)d_in[11];
    const float* W2    = (const float*)d_in[12];
    const float* b2    = (const float*)d_in[13];
    const float* ln2g  = (const float*)d_in[14];
    const float* ln2b  = (const float*)d_in[15];
    float* out = (float*)d_out;

    void *px_, *pqh_, *pkh_, *pvh_, *poh_, *pof_, *pt1_, *px1_, *phh_, *pt2_;
    cudaGetSymbolAddress(&px_,  g_x);
    cudaGetSymbolAddress(&pqh_, g_qh);
    cudaGetSymbolAddress(&pkh_, g_kh);
    cudaGetSymbolAddress(&pvh_, g_vh);
    cudaGetSymbolAddress(&poh_, g_oh);
    cudaGetSymbolAddress(&pof_, g_of);
    cudaGetSymbolAddress(&pt1_, g_t1);
    cudaGetSymbolAddress(&px1_, g_x1);
    cudaGetSymbolAddress(&phh_, g_hh);
    cudaGetSymbolAddress(&pt2_, g_t2);
    float* px  = (float*)px_;
    float* pqh = (float*)pqh_;
    float* pkh = (float*)pkh_;
    float* pvh = (float*)pvh_;
    float* poh = (float*)poh_;
    float* pof = (float*)pof_;
    float* pt1 = (float*)pt1_;
    float* px1 = (float*)px1_;
    float* phh = (float*)phh_;
    float* pt2 = (float*)pt2_;

    copy_kernel<<<NTQ*EDIM/256, 256>>>(query, px, NTQ*EDIM);

    const float scale = 0.17677669529663687f;  // 1/sqrt(32)
    for (int l = 0; l < NLAYER; l++) {
        const float* Wq = Wqkv + (size_t)l*3*EDIM*EDIM;
        const float* Wk = Wq + EDIM*EDIM;
        const float* Wv = Wq + 2*EDIM*EDIM;
        const float* bq = bqkv + (size_t)l*3*EDIM;
        const float* bk = bq + EDIM;
        const float* bv = bq + 2*EDIM;

        gemm_rope_kernel<true ><<<dim3(NTQ/128,  2), 256>>>(px,    Wq, bq, qpos,    pqh, LQ,  scale);
        gemm_rope_kernel<true ><<<dim3(NTKV/128, 2), 256>>>(value, Wk, bk, vpos,    pkh, LKV, 1.0f);
        gemm_rope_kernel<false><<<dim3(NTKV/128, 2), 256>>>(value, Wv, bv, nullptr, pvh, LKV, 1.0f);

        attn_kernel<<<dim3(LQ/64, BATCH*NHEAD), 256>>>(pqh, pkh, pvh, poh);
        reshape_kernel<<<NTQ*EDIM/256, 256>>>(poh, pof);

        gemm_gen_kernel<false,true ><<<dim3(NTQ/64, 4), 256>>>(pof, Wo + (size_t)l*EDIM*EDIM, bo + l*EDIM, px,  pt1);
        ln_kernel<<<NTQ, 256>>>(pt1, ln1g + l*EDIM, ln1b + l*EDIM, px1, nullptr);

        gemm_gen_kernel<true ,false><<<dim3(NTQ/64, 4), 256>>>(px1, W1 + (size_t)l*EDIM*EDIM, b1 + l*EDIM, nullptr, phh);
        gemm_gen_kernel<false,true ><<<dim3(NTQ/64, 4), 256>>>(phh, W2 + (size_t)l*EDIM*EDIM, b2 + l*EDIM, px1, pt2);
        ln_kernel<<<NTQ, 256>>>(pt2, ln2g + l*EDIM, ln2b + l*EDIM, px, out + (size_t)l*NTQ*EDIM);
    }
}